// round 1
// baseline (speedup 1.0000x reference)
#include <cuda_runtime.h>
#include <math.h>
#include <stdint.h>

#define BB 8
#define NN 16384
#define PP 512
#define DD 64
#define PTILE 64
#define NSUB 64
#define NCHUNKS 16
#define CHUNK (NN / NCHUNKS)   /* 1024 */

// Scratch (allocation-free rule: __device__ globals)
__device__ float g_pt[DD * PP];                 // normalized prototypes, transposed [d][p]
__device__ float g_p2[PP];                      // ||p||^2 after normalization
__device__ float g_x2[BB * NN];                 // ||x||^2 per patch
__device__ unsigned long long g_packed[BB * PP]; // (sq_bits<<32) | n  (min-reduced)

// ---------------------------------------------------------------------------
// prep: normalize prototypes (F.normalize semantics), store transposed, p2,
//       and init the packed min buffer.
// grid: 64 blocks x 256 threads  (512 warps = 512 prototypes; 16384 threads >= 4096 inits)
// ---------------------------------------------------------------------------
__global__ void prep_kernel(const float* __restrict__ proto) {
    int t = blockIdx.x * blockDim.x + threadIdx.x;
    if (t < BB * PP) g_packed[t] = 0xFFFFFFFFFFFFFFFFull;

    int gw = t >> 5;          // prototype index
    int lane = t & 31;
    if (gw >= PP) return;

    float2 v = ((const float2*)(proto + gw * DD))[lane];
    float s = v.x * v.x + v.y * v.y;
    #pragma unroll
    for (int o = 16; o; o >>= 1) s += __shfl_xor_sync(0xFFFFFFFFu, s, o);
    float inv = 1.0f / fmaxf(sqrtf(s), 1e-12f);
    float a = v.x * inv, b = v.y * inv;
    g_pt[(2 * lane + 0) * PP + gw] = a;
    g_pt[(2 * lane + 1) * PP + gw] = b;
    float q = a * a + b * b;
    #pragma unroll
    for (int o = 16; o; o >>= 1) q += __shfl_xor_sync(0xFFFFFFFFu, q, o);
    if (lane == 0) g_p2[gw] = q;
}

// ---------------------------------------------------------------------------
// x2: ||x||^2 per (b, n). One warp per row, float2 per lane, shfl reduce.
// grid: BB*NN/8 blocks x 256 threads
// ---------------------------------------------------------------------------
__global__ void x2_kernel(const float* __restrict__ x) {
    int gw = (blockIdx.x * blockDim.x + threadIdx.x) >> 5;
    int lane = threadIdx.x & 31;
    if (gw >= BB * NN) return;
    float2 v = ((const float2*)(x + (size_t)gw * DD))[lane];
    float s = fmaf(v.x, v.x, v.y * v.y);
    #pragma unroll
    for (int o = 16; o; o >>= 1) s += __shfl_xor_sync(0xFFFFFFFFu, s, o);
    if (lane == 0) g_x2[gw] = s;
}

// ---------------------------------------------------------------------------
// main: 64x64 tile GEMM (x . p^T) with min/argmin epilogue per n-subtile.
// grid: (NCHUNKS, PP/PTILE, BB) x 256 threads. 4x4 micro-tile per thread.
// ---------------------------------------------------------------------------
__global__ void __launch_bounds__(256)
main_kernel(const float* __restrict__ x) {
    __shared__ float4 ps4[DD * (PTILE / 4)];   // [d][p/4]   16 KB, loaded once
    __shared__ float4 xs4[NSUB * (DD / 4)];    // [n][d/4]   16 KB, per subtile
    __shared__ float p2s[PTILE];
    __shared__ unsigned long long red[PTILE];

    const int bb = blockIdx.z;
    const int pt = blockIdx.y * PTILE;
    const int n0 = blockIdx.x * CHUNK;
    const int tid = threadIdx.x;
    const int tx = tid & 15;        // p group: p = pt + tx*4 + j
    const int ty = tid >> 4;        // n group: n = nsub + ty*4 + i

    // prototype tile (transposed layout in gmem -> direct coalesced copy)
    for (int i = tid; i < DD * (PTILE / 4); i += 256) {
        int d = i / (PTILE / 4);
        int pg = i % (PTILE / 4);
        ps4[i] = ((const float4*)(g_pt + d * PP + pt))[pg];
    }
    if (tid < PTILE) {
        p2s[tid] = g_p2[pt + tid];
        red[tid] = 0xFFFFFFFFFFFFFFFFull;
    }

    unsigned long long best0 = ~0ull, best1 = ~0ull, best2 = ~0ull, best3 = ~0ull;

    const float* xb = x + (size_t)bb * NN * DD;
    const float* x2b = g_x2 + bb * NN;

    for (int ns = 0; ns < CHUNK; ns += NSUB) {
        __syncthreads();
        // load 64x64 x subtile: 1024 float4, 4 per thread, fully coalesced
        const float4* src = (const float4*)(xb + (size_t)(n0 + ns) * DD);
        #pragma unroll
        for (int k = 0; k < 4; k++) xs4[tid + k * 256] = src[tid + k * 256];
        __syncthreads();

        float S[4][4];
        #pragma unroll
        for (int i = 0; i < 4; i++)
            #pragma unroll
            for (int j = 0; j < 4; j++) S[i][j] = 0.0f;

        #pragma unroll
        for (int d4 = 0; d4 < DD / 4; d4++) {
            float4 af[4];
            #pragma unroll
            for (int i = 0; i < 4; i++) af[i] = xs4[(ty * 4 + i) * 16 + d4];
            #pragma unroll
            for (int dd = 0; dd < 4; dd++) {
                float4 bv = ps4[(d4 * 4 + dd) * 16 + tx];
                #pragma unroll
                for (int i = 0; i < 4; i++) {
                    float a = ((const float*)&af[i])[dd];
                    S[i][0] = fmaf(a, bv.x, S[i][0]);
                    S[i][1] = fmaf(a, bv.y, S[i][1]);
                    S[i][2] = fmaf(a, bv.z, S[i][2]);
                    S[i][3] = fmaf(a, bv.w, S[i][3]);
                }
            }
        }

        // min/argmin epilogue over this subtile's 4 n's x 4 p's
        const int nbase = n0 + ns + ty * 4;
        #pragma unroll
        for (int i = 0; i < 4; i++) {
            float x2v = __ldg(&x2b[nbase + i]);
            unsigned long long nidx = (unsigned long long)(unsigned)(nbase + i);
            #pragma unroll
            for (int j = 0; j < 4; j++) {
                float sq = fmaxf(x2v - 2.0f * S[i][j] + p2s[tx * 4 + j], 0.0f);
                unsigned long long key =
                    ((unsigned long long)__float_as_uint(sq) << 32) | nidx;
                if (j == 0) best0 = key < best0 ? key : best0;
                if (j == 1) best1 = key < best1 ? key : best1;
                if (j == 2) best2 = key < best2 ? key : best2;
                if (j == 3) best3 = key < best3 ? key : best3;
            }
        }
    }

    __syncthreads();
    atomicMin(&red[tx * 4 + 0], best0);
    atomicMin(&red[tx * 4 + 1], best1);
    atomicMin(&red[tx * 4 + 2], best2);
    atomicMin(&red[tx * 4 + 3], best3);
    __syncthreads();
    if (tid < PTILE) atomicMin(&g_packed[bb * PP + pt + tid], red[tid]);
}

// ---------------------------------------------------------------------------
// unpack: packed (sq,idx) -> out[dist(B,P)] ++ out[idx(B,P) as float]
// ---------------------------------------------------------------------------
__global__ void unpack_kernel(float* __restrict__ out) {
    int t = blockIdx.x * blockDim.x + threadIdx.x;
    if (t >= BB * PP) return;
    unsigned long long k = g_packed[t];
    float sq = __uint_as_float((unsigned)(k >> 32));
    unsigned idx = (unsigned)(k & 0xFFFFFFFFu);
    out[t] = sqrtf(sq + 1e-8f);
    out[BB * PP + t] = (float)idx;
}

extern "C" void kernel_launch(void* const* d_in, const int* in_sizes, int n_in,
                              void* d_out, int out_size) {
    const float* x = (const float*)d_in[0];
    const float* proto = (const float*)d_in[1];
    float* out = (float*)d_out;

    prep_kernel<<<64, 256>>>(proto);
    x2_kernel<<<(BB * NN) / 8, 256>>>(x);
    dim3 grid(NCHUNKS, PP / PTILE, BB);
    main_kernel<<<grid, 256>>>(x);
    unpack_kernel<<<(BB * PP + 255) / 256, 256>>>(out);
}